// round 14
// baseline (speedup 1.0000x reference)
#include <cuda_runtime.h>
#include <math.h>

#define B 8
#define M 12
#define NN 32
#define D 256
#define C 1024      // N*N
#define CH 512      // C/R
#define BM 96
#define GRID 148
#define NT 512

typedef unsigned long long ull;

// Scratch (allocation-free rule: device globals)
__device__ float g_S[BM * NN];     // row sums per bm
__device__ float g_U[NN * CH];     // [n][o] collapsed-GEMM1 weights
__device__ float g_cov[BM * C];    // centered cov (sign -> mask)
__device__ float g_ev[BM * C];     // exp(sigmoid(e2)), pre-mask
__device__ unsigned g_bcnt;        // barrier counter (returns to 0 each barrier)
__device__ volatile int g_bflag;   // barrier sense (0 -> 1 -> 0 per run)
__device__ float g_junkf;          // keeps W2 prefetch loads alive

// ---- packed f32x2 helpers -------------------------------------------------
__device__ __forceinline__ ull ffma2(ull a, ull b, ull c) {
    ull d_;
    asm("fma.rn.f32x2 %0, %1, %2, %3;" : "=l"(d_) : "l"(a), "l"(b), "l"(c));
    return d_;
}
__device__ __forceinline__ ull pk2(float lo, float hi) {
    ull r;
    asm("mov.b64 %0, {%1, %2};" : "=l"(r) : "f"(lo), "f"(hi));
    return r;
}
__device__ __forceinline__ float unpk_add(ull v) {
    float lo, hi;
    asm("mov.b64 {%0, %1}, %2;" : "=f"(lo), "=f"(hi) : "l"(v));
    return lo + hi;
}
__device__ __forceinline__ void unpk2(ull v, float& lo, float& hi) {
    asm("mov.b64 {%0, %1}, %2;" : "=f"(lo), "=f"(hi) : "l"(v));
}

// smem swizzle: q in [0,128) float4 units within a 512-float row
#define SWZ(q) (((q) & 0x70) | (((q) ^ ((q) >> 4)) & 0x0F))
#define SWZ4(o) (SWZ((o) >> 2) * 4 + ((o) & 3))
#define XPAD 260   // floats per padded x row (= 65 float4)

// Grid-wide sense-reversing barrier. Safe: grid == 148 == one full wave.
__device__ __forceinline__ void gbar(int sense) {
    __syncthreads();
    if (threadIdx.x == 0) {
        __threadfence();
        if (atomicAdd(&g_bcnt, 1) == GRID - 1) {
            g_bcnt = 0;
            __threadfence();
            g_bflag = sense;
        } else {
            while (g_bflag != sense) __nanosleep(64);
        }
        __threadfence();
    }
    __syncthreads();
}

// ---------------------------------------------------------------------------
__global__ void __launch_bounds__(NT) kFused(const float* __restrict__ x,
                                             const float* __restrict__ W1,
                                             const float* __restrict__ W2,
                                             float* __restrict__ out) {
    extern __shared__ float sm[];
    const int bid = blockIdx.x;
    const int tid = threadIdx.x;
    const int w = tid >> 5, lane = tid & 31;

    // ======================= PHASE 1 =======================
    if (bid < BM) {
        // ---- per-bm: one x pass -> S + full 32x32 centered cov ----
        const int bm = bid;
        const int g = w >> 3, wg = w & 7;
        float* xs  = sm;             // padded natural [n*XPAD + d], 8320
        float* red = sm + 8320;      // 16 warps x 512 = 8192
        float* sp  = sm + 16512;     // 256
        float* S   = sm + 16768;     // 32

        const float4* xg4 = (const float4*)(x + (size_t)bm * (NN * D));
        float4* xs4 = (float4*)xs;
        #pragma unroll
        for (int t = 0; t < 4; t++) {
            const int i = tid + t * NT;
            const int n = i >> 6, q = i & 63;
            xs4[n * 65 + q] = xg4[i];    // conflict-free STS.128
        }
        __syncthreads();

        // xk = x[k=lane][wg*32 .. wg*32+31] via 8 LDS.128
        ull xk2[16];
        float spv = 0.f;
        const float4* xrow4 = (const float4*)(xs + lane * XPAD + wg * 32);
        #pragma unroll
        for (int j = 0; j < 8; j++) {
            const float4 v = xrow4[j];
            xk2[2 * j]     = pk2(v.x, v.y);
            xk2[2 * j + 1] = pk2(v.z, v.w);
            spv += (v.x + v.y) + (v.z + v.w);
        }
        if (g == 0) sp[wg * 32 + lane] = spv;
        __syncthreads();
        if (tid < 32) {
            float s = 0.f;
            #pragma unroll
            for (int ww = 0; ww < 8; ww++) s += sp[ww * 32 + tid];
            S[tid] = s;
            g_S[bm * NN + tid] = s;
        }
        __syncthreads();

        // cov partials for n in [g*16, g*16+16)
        ull acc2[16];
        #pragma unroll
        for (int nn = 0; nn < 16; nn++) acc2[nn] = 0ull;

        const ulonglong2* xs2 = (const ulonglong2*)xs;   // rows stride 65 f4
        #pragma unroll
        for (int nn = 0; nn < 16; nn++) {
            const ulonglong2* rowp = xs2 + (g * 16 + nn) * 65 + wg * 8;
            #pragma unroll
            for (int jj = 0; jj < 8; jj++) {
                const ulonglong2 bv = rowp[jj];          // broadcast LDS.128
                acc2[nn] = ffma2(bv.x, xk2[2 * jj], acc2[nn]);
                acc2[nn] = ffma2(bv.y, xk2[2 * jj + 1], acc2[nn]);
            }
        }
        #pragma unroll
        for (int nn = 0; nn < 16; nn++)
            red[w * 512 + nn * 32 + lane] = unpk_add(acc2[nn]);
        __syncthreads();

        if (tid < 256) {   // combine 8 d-chunk partials of the right group
            const float4* red4 = (const float4*)red;
            const int n = tid >> 3, kq = tid & 7;
            const int gn = n >> 4, nl = n & 15;
            float4 cv = make_float4(0.f, 0.f, 0.f, 0.f);
            #pragma unroll
            for (int ww = 0; ww < 8; ww++) {
                const float4 t = red4[(gn * 8 + ww) * 128 + nl * 8 + kq];
                cv.x += t.x; cv.y += t.y; cv.z += t.z; cv.w += t.w;
            }
            const int k0 = kq * 4;
            const float sn = S[n] * (1.f / 256.f);
            cv.x -= sn * S[k0 + 0]; cv.y -= sn * S[k0 + 1];
            cv.z -= sn * S[k0 + 2]; cv.w -= sn * S[k0 + 3];
            ((float4*)(g_cov + (size_t)bm * C))[tid] = cv;
        }
    } else {
        // ---- U blocks (52): o-chunks of 10, then W2 L2-prefetch ----
        const int ub = bid - BM;
        float* smT = sm + w * 1056;   // per-warp 33x32 transpose buf

        if (w < 10) {
            const int o = ub * 10 + w;
            if (o < CH) {
                const float* row = W1 + (size_t)o * C;
                float rr[32], cs = 0.f;
                #pragma unroll
                for (int j = 0; j < 32; j++) { rr[j] = row[j * 32 + lane]; cs += rr[j]; }
                #pragma unroll
                for (int j = 0; j < 32; j++) smT[j * 33 + lane] = rr[j];
                __syncwarp();
                float rs = 0.f;
                #pragma unroll
                for (int mm = 0; mm < 32; mm++) rs += smT[lane * 33 + mm];
                const float dg = smT[lane * 33 + lane];
                g_U[lane * CH + o] = rs + 2.f * cs - dg;   // lane = n
            }
        }

        // W2 prefetch into L2 (overlaps phase-1 compute elsewhere)
        const float4* w2g4 = (const float4*)W2;
        float s = 0.f;
        #pragma unroll
        for (int j = 0; j < 5; j++) {
            const int idx = ub * NT + tid + j * 26624;
            if (idx < 131072) {
                const float4 v = w2g4[idx];
                s += (v.x + v.y) + (v.z + v.w);
            }
        }
        if (__float_as_uint(s) == 0xDEADBEEFu) g_junkf = s;  // never true; keeps loads
    }

    gbar(1);

    // ======================= PHASE 2: e2 (blocks 0..127) =======================
    if (bid < 128) {
        const int ct = bid >> 3, b = bid & 7;
        float* hs   = sm;                    // 12 x 512 swizzled = 6144
        float* S12t = sm + 6144;             // [n*12 + m], 384
        float* part = sm + 6528;             // [kc][c*12+m], 8 x 771 = 6168

        if (tid < 384) {
            const int m = tid >> 5, n = tid & 31;
            S12t[n * 12 + m] = g_S[(b * M + m) * NN + n];
        }
        __syncthreads();

        // h inline: thread owns o = tid
        {
            ull hacc[6];
            #pragma unroll
            for (int mm = 0; mm < 6; mm++) hacc[mm] = 0ull;
            #pragma unroll 4
            for (int n = 0; n < 32; n++) {
                const float u = g_U[n * CH + tid];
                const ull uu = pk2(u, u);
                #pragma unroll
                for (int mm = 0; mm < 6; mm++) {
                    const ull sv = *(const ull*)(S12t + n * 12 + 2 * mm);
                    hacc[mm] = ffma2(sv, uu, hacc[mm]);
                }
            }
            const int so = SWZ4(tid);
            #pragma unroll
            for (int mm = 0; mm < 6; mm++) {
                float a, bb;
                unpk2(hacc[mm], a, bb);
                hs[(2 * mm) * 512 + so]     = fmaxf(a  * (1.f / 512.f), 0.f);
                hs[(2 * mm + 1) * 512 + so] = fmaxf(bb * (1.f / 512.f), 0.f);
            }
        }
        __syncthreads();

        const int c  = tid >> 3;          // 0..63 (row of W2 tile)
        const int kc = tid & 7;           // k-chunk of 64 floats
        const int kc16 = kc * 16;
        const ulonglong2* hu = (const ulonglong2*)hs;
        // W2 straight from global (L2-warm via phase-1 prefetch)
        const ulonglong2* w2r = (const ulonglong2*)(W2 + (size_t)(ct * 64 + c) * CH);

        ull acc[12];
        #pragma unroll
        for (int m = 0; m < 12; m++) acc[m] = 0ull;

        #pragma unroll 4
        for (int j = 0; j < 16; j++) {
            const ulonglong2 wv = w2r[kc16 + j];                 // LDG (L2)
            const int qs = kc16 + ((j ^ kc) & 15);               // = SWZ(kc16+j)
            #pragma unroll
            for (int m = 0; m < 12; m++) {
                const ulonglong2 hv = hu[m * 128 + qs];          // 1-wf LDS
                acc[m] = ffma2(wv.x, hv.x, acc[m]);
                acc[m] = ffma2(wv.y, hv.y, acc[m]);
            }
        }
        __syncthreads();   // hs reads done before part overwrites? (separate region; sync for S12t reuse safety)

        #pragma unroll
        for (int m = 0; m < 12; m++)
            part[kc * 771 + c * 12 + m] = unpk_add(acc[m]);
        __syncthreads();

        #pragma unroll
        for (int t = 0; t < 2; t++) {
            const int i2 = tid + t * NT;        // = cc*12 + m, cc in 0..63
            if (i2 < 768) {
                const int cc = i2 / 12, m = i2 - 12 * cc;
                float e2v = 0.f;
                #pragma unroll
                for (int kk = 0; kk < 8; kk++) e2v += part[kk * 771 + i2];
                const float sg = 1.f / (1.f + __expf(-e2v));
                g_ev[(size_t)(b * M + m) * C + ct * 64 + cc] = __expf(sg);
            }
        }
    }

    gbar(0);

    // ======================= PHASE 3: out (blocks 0..95) =======================
    if (bid < BM) {
        const int bm = bid;
        const int half = tid >> 8, dd = tid & 255;
        float* att  = sm;          // 1024 (un-normalized masked exp)
        float* rinv = sm + 1024;   // 32

        // x column dd into regs (L2-warm after phase 1)
        const float* xp = x + (size_t)bm * (NN * D) + dd;
        float xv[NN];
        #pragma unroll
        for (int k = 0; k < NN; k++) xv[k] = __ldg(xp + k * D);

        if (tid < 256) {
            const float4 cv4 = ((const float4*)(g_cov + (size_t)bm * C))[tid];
            const float4 ev4 = ((const float4*)(g_ev + (size_t)bm * C))[tid];
            float4 a;
            a.x = (cv4.x > 0.f) ? ev4.x : 0.f;
            a.y = (cv4.y > 0.f) ? ev4.y : 0.f;
            a.z = (cv4.z > 0.f) ? ev4.z : 0.f;
            a.w = (cv4.w > 0.f) ? ev4.w : 0.f;
            ((float4*)att)[tid] = a;
        }
        __syncthreads();

        {   // row sums -> inverses: warp w handles rows 2w, 2w+1
            float v[2];
            #pragma unroll
            for (int r = 0; r < 2; r++) v[r] = att[(w * 2 + r) * NN + lane];
            #pragma unroll
            for (int off = 16; off; off >>= 1) {
                #pragma unroll
                for (int r = 0; r < 2; r++)
                    v[r] += __shfl_xor_sync(0xffffffffu, v[r], off);
            }
            #pragma unroll
            for (int r = 0; r < 2; r++)
                if (lane == 0) rinv[w * 2 + r] = 1.f / v[r];
        }
        __syncthreads();

        ull xv2[16];
        #pragma unroll
        for (int kk = 0; kk < 16; kk++) xv2[kk] = pk2(xv[2 * kk], xv[2 * kk + 1]);

        float* ot = out + (size_t)bm * (NN * D) + half * 16 * D;
        #pragma unroll 4
        for (int nn = 0; nn < 16; nn++) {
            const int n = half * 16 + nn;
            const ulonglong2* ar = (const ulonglong2*)(att + n * NN);
            ull a2 = 0ull;
            #pragma unroll
            for (int jj = 0; jj < 8; jj++) {
                const ulonglong2 bv = ar[jj];        // broadcast LDS.128
                a2 = ffma2(bv.x, xv2[2 * jj], a2);
                a2 = ffma2(bv.y, xv2[2 * jj + 1], a2);
            }
            ot[nn * D + dd] = unpk_add(a2) * rinv[n];
        }
    }
}

// ---------------------------------------------------------------------------
extern "C" void kernel_launch(void* const* d_in, const int* in_sizes, int n_in,
                              void* d_out, int out_size) {
    const float* x  = (const float*)d_in[0];
    const float* W1 = (const float*)d_in[1];
    const float* W2 = (const float*)d_in[2];
    float* out = (float*)d_out;

    const int smem = 16800 * sizeof(float);   // 67,200 B (phase-1 high-water)
    cudaFuncSetAttribute(kFused, cudaFuncAttributeMaxDynamicSharedMemorySize, smem);

    kFused<<<GRID, NT, smem>>>(x, W1, W2, out);
}

// round 15
// speedup vs baseline: 1.0767x; 1.0767x over previous
#include <cuda_runtime.h>
#include <math.h>

#define B 8
#define M 12
#define NN 32
#define D 256
#define C 1024      // N*N
#define CH 512      // C/R
#define BM 96
#define GRID 148
#define NT 512

typedef unsigned long long ull;

// Scratch (allocation-free rule: device globals)
__device__ float g_S[BM * NN];     // row sums per bm
__device__ float g_U[NN * CH];     // [n][o] collapsed-GEMM1 weights
__device__ float g_cov[BM * C];    // centered cov (sign -> mask)
__device__ float g_ev[BM * C];     // exp(sigmoid(e2)), pre-mask
__device__ unsigned g_bcnt;        // barrier counter (returns to 0 each barrier)
__device__ volatile int g_bflag;   // barrier sense (0 -> 1 -> 0 per run)

// ---- packed f32x2 helpers -------------------------------------------------
__device__ __forceinline__ ull ffma2(ull a, ull b, ull c) {
    ull d_;
    asm("fma.rn.f32x2 %0, %1, %2, %3;" : "=l"(d_) : "l"(a), "l"(b), "l"(c));
    return d_;
}
__device__ __forceinline__ ull pk2(float lo, float hi) {
    ull r;
    asm("mov.b64 %0, {%1, %2};" : "=l"(r) : "f"(lo), "f"(hi));
    return r;
}
__device__ __forceinline__ float unpk_add(ull v) {
    float lo, hi;
    asm("mov.b64 {%0, %1}, %2;" : "=f"(lo), "=f"(hi) : "l"(v));
    return lo + hi;
}
__device__ __forceinline__ void unpk2(ull v, float& lo, float& hi) {
    asm("mov.b64 {%0, %1}, %2;" : "=f"(lo), "=f"(hi) : "l"(v));
}

// smem swizzle: q in [0,128) float4 units within a 512-float row
#define SWZ(q) (((q) & 0x70) | (((q) ^ ((q) >> 4)) & 0x0F))
#define SWZ4(o) (SWZ((o) >> 2) * 4 + ((o) & 3))
#define XPAD 260   // floats per padded x row (= 65 float4)

// Grid-wide sense-reversing barrier. Safe: grid == 148 == one full wave.
__device__ __forceinline__ void gbar(int sense) {
    __syncthreads();
    if (threadIdx.x == 0) {
        __threadfence();
        if (atomicAdd(&g_bcnt, 1) == GRID - 1) {
            g_bcnt = 0;
            __threadfence();
            g_bflag = sense;
        } else {
            while (g_bflag != sense) __nanosleep(32);
        }
        __threadfence();
    }
    __syncthreads();
}

// ---------------------------------------------------------------------------
__global__ void __launch_bounds__(NT) kFused(const float* __restrict__ x,
                                             const float* __restrict__ W1,
                                             const float* __restrict__ W2,
                                             float* __restrict__ out) {
    extern __shared__ float sm[];
    const int bid = blockIdx.x;
    const int tid = threadIdx.x;
    const int w = tid >> 5, lane = tid & 31;

    // ======================= PHASE 1 =======================
    if (bid < BM) {
        // ---- per-bm: one x pass -> S + full 32x32 centered cov ----
        const int bm = bid;
        const int g = w >> 3, wg = w & 7;
        float* xs  = sm;             // padded natural [n*XPAD + d], 8320
        float* red = sm + 8320;      // 16 warps x 512 = 8192
        float* sp  = sm + 16512;     // 256
        float* S   = sm + 16768;     // 32

        const float4* xg4 = (const float4*)(x + (size_t)bm * (NN * D));
        float4* xs4 = (float4*)xs;
        #pragma unroll
        for (int t = 0; t < 4; t++) {
            const int i = tid + t * NT;
            const int n = i >> 6, q = i & 63;
            xs4[n * 65 + q] = xg4[i];    // conflict-free STS.128
        }
        __syncthreads();

        // xk = x[k=lane][wg*32 .. wg*32+31] via 8 LDS.128
        ull xk2[16];
        float spv = 0.f;
        const float4* xrow4 = (const float4*)(xs + lane * XPAD + wg * 32);
        #pragma unroll
        for (int j = 0; j < 8; j++) {
            const float4 v = xrow4[j];
            xk2[2 * j]     = pk2(v.x, v.y);
            xk2[2 * j + 1] = pk2(v.z, v.w);
            spv += (v.x + v.y) + (v.z + v.w);
        }
        if (g == 0) sp[wg * 32 + lane] = spv;
        __syncthreads();
        if (tid < 32) {
            float s = 0.f;
            #pragma unroll
            for (int ww = 0; ww < 8; ww++) s += sp[ww * 32 + tid];
            S[tid] = s;
            g_S[bm * NN + tid] = s;
        }
        __syncthreads();

        // cov partials for n in [g*16, g*16+16)
        ull acc2[16];
        #pragma unroll
        for (int nn = 0; nn < 16; nn++) acc2[nn] = 0ull;

        const ulonglong2* xs2 = (const ulonglong2*)xs;   // rows stride 65 f4
        #pragma unroll
        for (int nn = 0; nn < 16; nn++) {
            const ulonglong2* rowp = xs2 + (g * 16 + nn) * 65 + wg * 8;
            #pragma unroll
            for (int jj = 0; jj < 8; jj++) {
                const ulonglong2 bv = rowp[jj];          // broadcast LDS.128
                acc2[nn] = ffma2(bv.x, xk2[2 * jj], acc2[nn]);
                acc2[nn] = ffma2(bv.y, xk2[2 * jj + 1], acc2[nn]);
            }
        }
        #pragma unroll
        for (int nn = 0; nn < 16; nn++)
            red[w * 512 + nn * 32 + lane] = unpk_add(acc2[nn]);
        __syncthreads();

        if (tid < 256) {   // combine 8 d-chunk partials of the right group
            const float4* red4 = (const float4*)red;
            const int n = tid >> 3, kq = tid & 7;
            const int gn = n >> 4, nl = n & 15;
            float4 cv = make_float4(0.f, 0.f, 0.f, 0.f);
            #pragma unroll
            for (int ww = 0; ww < 8; ww++) {
                const float4 t = red4[(gn * 8 + ww) * 128 + nl * 8 + kq];
                cv.x += t.x; cv.y += t.y; cv.z += t.z; cv.w += t.w;
            }
            const int k0 = kq * 4;
            const float sn = S[n] * (1.f / 256.f);
            cv.x -= sn * S[k0 + 0]; cv.y -= sn * S[k0 + 1];
            cv.z -= sn * S[k0 + 2]; cv.w -= sn * S[k0 + 3];
            ((float4*)(g_cov + (size_t)bm * C))[tid] = cv;
        }
    } else {
        // ---- U blocks (52): o-chunks of 10; NO W2 prefetch (phase 2 reads it) ----
        const int ub = bid - BM;
        float* smT = sm + w * 1056;   // per-warp 33x32 transpose buf

        if (w < 10) {
            const int o = ub * 10 + w;
            if (o < CH) {
                const float* row = W1 + (size_t)o * C;
                float rr[32], cs = 0.f;
                #pragma unroll
                for (int j = 0; j < 32; j++) { rr[j] = row[j * 32 + lane]; cs += rr[j]; }
                #pragma unroll
                for (int j = 0; j < 32; j++) smT[j * 33 + lane] = rr[j];
                __syncwarp();
                float rs = 0.f;
                #pragma unroll
                for (int mm = 0; mm < 32; mm++) rs += smT[lane * 33 + mm];
                const float dg = smT[lane * 33 + lane];
                g_U[lane * CH + o] = rs + 2.f * cs - dg;   // lane = n
            }
        }
    }

    gbar(1);

    // ======================= PHASE 2: e2 (blocks 0..127) =======================
    if (bid < 128) {
        const int ct = bid >> 3, b = bid & 7;
        float* W2s  = sm;                    // 64 x 512 swizzled = 32768
        float* hs   = sm + 32768;            // 12 x 512 swizzled = 6144
        float* S12t = sm + 38912;            // [n*12 + m], 384

        const float4* w2g = (const float4*)(W2 + (size_t)(ct * 64) * CH);

        #pragma unroll
        for (int t = 0; t < 16; t++) {       // full 64-row tile, one pass (cold->L2 dedup)
            const int i = tid + t * NT;
            const int r = i >> 7, q = i & 127;
            ((float4*)W2s)[r * 128 + SWZ(q)] = w2g[i];
        }
        if (tid < 384) {
            const int m = tid >> 5, n = tid & 31;
            S12t[n * 12 + m] = g_S[(b * M + m) * NN + n];
        }
        __syncthreads();

        // h inline: thread owns o = tid
        {
            ull hacc[6];
            #pragma unroll
            for (int mm = 0; mm < 6; mm++) hacc[mm] = 0ull;
            #pragma unroll 4
            for (int n = 0; n < 32; n++) {
                const float u = g_U[n * CH + tid];
                const ull uu = pk2(u, u);
                #pragma unroll
                for (int mm = 0; mm < 6; mm++) {
                    const ull sv = *(const ull*)(S12t + n * 12 + 2 * mm);
                    hacc[mm] = ffma2(sv, uu, hacc[mm]);
                }
            }
            const int so = SWZ4(tid);
            #pragma unroll
            for (int mm = 0; mm < 6; mm++) {
                float a, bb;
                unpk2(hacc[mm], a, bb);
                hs[(2 * mm) * 512 + so]     = fmaxf(a  * (1.f / 512.f), 0.f);
                hs[(2 * mm + 1) * 512 + so] = fmaxf(bb * (1.f / 512.f), 0.f);
            }
        }
        __syncthreads();

        const int c  = tid >> 3;          // 0..63 (row of W2 tile)
        const int kc = tid & 7;           // k-chunk of 64 floats
        const int kc16 = kc * 16;
        const ulonglong2* hu = (const ulonglong2*)hs;
        const ulonglong2* Wu = (const ulonglong2*)W2s;

        ull acc[12];
        #pragma unroll
        for (int m = 0; m < 12; m++) acc[m] = 0ull;

        #pragma unroll 4
        for (int j = 0; j < 16; j++) {
            const int qs = kc16 + ((j ^ kc) & 15);
            const ulonglong2 wv = Wu[c * 128 + qs];
            #pragma unroll
            for (int m = 0; m < 12; m++) {
                const ulonglong2 hv = hu[m * 128 + qs];
                acc[m] = ffma2(wv.x, hv.x, acc[m]);
                acc[m] = ffma2(wv.y, hv.y, acc[m]);
            }
        }
        __syncthreads();   // done with W2s; reuse as partials

        float* part = W2s;   // [kc][row*12+m], row in 0..63, stride 771
        #pragma unroll
        for (int m = 0; m < 12; m++)
            part[kc * 771 + c * 12 + m] = unpk_add(acc[m]);
        __syncthreads();

        #pragma unroll
        for (int t = 0; t < 2; t++) {
            const int i2 = tid + t * NT;        // = cc*12 + m, cc in 0..63
            if (i2 < 768) {
                const int cc = i2 / 12, m = i2 - 12 * cc;
                float e2v = 0.f;
                #pragma unroll
                for (int kk = 0; kk < 8; kk++) e2v += part[kk * 771 + i2];
                const float sg = 1.f / (1.f + __expf(-e2v));
                g_ev[(size_t)(b * M + m) * C + ct * 64 + cc] = __expf(sg);
            }
        }
    }

    gbar(0);

    // ======================= PHASE 3: out (blocks 0..95) =======================
    if (bid < BM) {
        const int bm = bid;
        const int half = tid >> 8, dd = tid & 255;
        float* att  = sm;          // 1024 (un-normalized masked exp)
        float* rinv = sm + 1024;   // 32

        // x column dd into regs (L2-warm after phase 1)
        const float* xp = x + (size_t)bm * (NN * D) + dd;
        float xv[NN];
        #pragma unroll
        for (int k = 0; k < NN; k++) xv[k] = __ldg(xp + k * D);

        if (tid < 256) {
            const float4 cv4 = ((const float4*)(g_cov + (size_t)bm * C))[tid];
            const float4 ev4 = ((const float4*)(g_ev + (size_t)bm * C))[tid];
            float4 a;
            a.x = (cv4.x > 0.f) ? ev4.x : 0.f;
            a.y = (cv4.y > 0.f) ? ev4.y : 0.f;
            a.z = (cv4.z > 0.f) ? ev4.z : 0.f;
            a.w = (cv4.w > 0.f) ? ev4.w : 0.f;
            ((float4*)att)[tid] = a;
        }
        __syncthreads();

        {   // row sums -> inverses: warp w handles rows 2w, 2w+1
            float v[2];
            #pragma unroll
            for (int r = 0; r < 2; r++) v[r] = att[(w * 2 + r) * NN + lane];
            #pragma unroll
            for (int off = 16; off; off >>= 1) {
                #pragma unroll
                for (int r = 0; r < 2; r++)
                    v[r] += __shfl_xor_sync(0xffffffffu, v[r], off);
            }
            #pragma unroll
            for (int r = 0; r < 2; r++)
                if (lane == 0) rinv[w * 2 + r] = 1.f / v[r];
        }
        __syncthreads();

        ull xv2[16];
        #pragma unroll
        for (int kk = 0; kk < 16; kk++) xv2[kk] = pk2(xv[2 * kk], xv[2 * kk + 1]);

        float* ot = out + (size_t)bm * (NN * D) + half * 16 * D;
        #pragma unroll 4
        for (int nn = 0; nn < 16; nn++) {
            const int n = half * 16 + nn;
            const ulonglong2* ar = (const ulonglong2*)(att + n * NN);
            ull a2 = 0ull;
            #pragma unroll
            for (int jj = 0; jj < 8; jj++) {
                const ulonglong2 bv = ar[jj];        // broadcast LDS.128
                a2 = ffma2(bv.x, xv2[2 * jj], a2);
                a2 = ffma2(bv.y, xv2[2 * jj + 1], a2);
            }
            ot[nn * D + dd] = unpk_add(a2) * rinv[n];
        }
    }
}

// ---------------------------------------------------------------------------
extern "C" void kernel_launch(void* const* d_in, const int* in_sizes, int n_in,
                              void* d_out, int out_size) {
    const float* x  = (const float*)d_in[0];
    const float* W1 = (const float*)d_in[1];
    const float* W2 = (const float*)d_in[2];
    float* out = (float*)d_out;

    const int smem = 39296 * sizeof(float);   // 157,184 B (phase-2 high-water)
    cudaFuncSetAttribute(kFused, cudaFuncAttributeMaxDynamicSharedMemorySize, smem);

    kFused<<<GRID, NT, smem>>>(x, W1, W2, out);
}